// round 1
// baseline (speedup 1.0000x reference)
#include <cuda_runtime.h>
#include <cuda_bf16.h>
#include <cstdint>

#define NROWS 8192
#define DDIM  256
#define BM 128
#define BN 64
#define SPLIT 4
#define NBUF (SPLIT*2)
// smem: A tile 128x256 bf16 (swizzled, 512B/row) + B tile 64x256 bf16 + 64 col labels
#define SMEM_A_BYTES (BM*512)
#define SMEM_B_BYTES (BN*512)
#define SMEM_BYTES (SMEM_A_BYTES + SMEM_B_BYTES + BN*4)

__device__ __align__(16) __nv_bfloat16 g_fn[NROWS*DDIM];
__device__ int   g_lab[NROWS];
__device__ float g_sumP[NBUF][NROWS];
__device__ float g_posP[NBUF][NROWS];
__device__ float g_cntP[NBUF][NROWS];

// ---------------- Phase 1: normalize rows, convert to bf16, labels -> int32 ---
__global__ void prep_kernel(const float* __restrict__ feat,
                            const long long* __restrict__ lab) {
    int row  = (blockIdx.x * blockDim.x + threadIdx.x) >> 5;
    int lane = threadIdx.x & 31;
    if (row >= NROWS) return;
    float v[8]; float ss = 0.f;
#pragma unroll
    for (int i = 0; i < 8; i++) {
        float x = feat[row*DDIM + i*32 + lane];
        v[i] = x; ss += x*x;
    }
#pragma unroll
    for (int o = 16; o > 0; o >>= 1) ss += __shfl_xor_sync(0xffffffffu, ss, o);
    float scale = 1.f / fmaxf(sqrtf(ss), 1e-6f);
#pragma unroll
    for (int i = 0; i < 8; i++)
        g_fn[row*DDIM + i*32 + lane] = __float2bfloat16(v[i]*scale);
    if (lane == 0) g_lab[row] = (int)lab[row];
}

// ---------------- mma.sync helpers -------------------------------------------
__device__ __forceinline__ void ldsm_x4(uint32_t& r0, uint32_t& r1, uint32_t& r2,
                                        uint32_t& r3, uint32_t addr) {
    asm volatile("ldmatrix.sync.aligned.m8n8.x4.shared.b16 {%0,%1,%2,%3}, [%4];\n"
                 : "=r"(r0), "=r"(r1), "=r"(r2), "=r"(r3) : "r"(addr));
}
__device__ __forceinline__ void mma16816(float& d0, float& d1, float& d2, float& d3,
                                         uint32_t a0, uint32_t a1, uint32_t a2,
                                         uint32_t a3, uint32_t b0, uint32_t b1) {
    asm volatile("mma.sync.aligned.m16n8k16.row.col.f32.bf16.bf16.f32 "
                 "{%0,%1,%2,%3}, {%4,%5,%6,%7}, {%8,%9}, {%0,%1,%2,%3};\n"
                 : "+f"(d0), "+f"(d1), "+f"(d2), "+f"(d3)
                 : "r"(a0), "r"(a1), "r"(a2), "r"(a3), "r"(b0), "r"(b1));
}

// ---------------- Phase 2: fused GEMM + softmax stats -------------------------
// grid = (NROWS/BM, SPLIT); 256 threads; 8 warps as 4(m) x 2(n), warp tile 32x32
__global__ void __launch_bounds__(256, 1) gemm_fused_kernel() {
    extern __shared__ char smem[];
    const uint32_t sA_u = (uint32_t)__cvta_generic_to_shared(smem);
    const uint32_t sB_u = sA_u + SMEM_A_BYTES;
    int* sLab = (int*)(smem + SMEM_A_BYTES + SMEM_B_BYTES);

    const int rowBase = blockIdx.x * BM;
    const int split   = blockIdx.y;
    const int tid  = threadIdx.x;
    const int warp = tid >> 5, lane = tid & 31;
    const int wm = warp >> 1, wn = warp & 1;
    const int g  = lane >> 2;
    const int q2 = (lane & 3) * 2;

    // Load A tile (persistent), SW-swizzled: chunk' = chunk ^ (row & 7)
    for (int idx = tid; idx < BM*32; idx += 256) {
        int r = idx >> 5, c = idx & 31;
        uint4 val = ((const uint4*)(g_fn + (size_t)(rowBase + r)*DDIM))[c];
        *((uint4*)(smem + r*512 + ((c ^ (r & 7)) << 4))) = val;
    }

    // rows this thread owns in the accumulator fragments
    int myrow[4], mylab[4];
#pragma unroll
    for (int mt = 0; mt < 2; mt++)
#pragma unroll
        for (int h = 0; h < 2; h++) {
            int rl = wm*32 + mt*16 + h*8 + g;
            myrow[mt*2+h] = rowBase + rl;
            mylab[mt*2+h] = g_lab[rowBase + rl];
        }

    float accS[4] = {0,0,0,0}, accP[4] = {0,0,0,0};
    int   accC[4] = {0,0,0,0};
    const float invT = 1.0f/0.07f;

    const int colsPer  = NROWS / SPLIT;
    const int colStart = split * colsPer;
    for (int jt = 0; jt < colsPer / BN; jt++) {
        const int colBase = colStart + jt * BN;
        __syncthreads();   // previous tile's compute done before overwriting B
        for (int idx = tid; idx < BN*32; idx += 256) {
            int r = idx >> 5, c = idx & 31;
            uint4 val = ((const uint4*)(g_fn + (size_t)(colBase + r)*DDIM))[c];
            *((uint4*)(smem + SMEM_A_BYTES + r*512 + ((c ^ (r & 7)) << 4))) = val;
        }
        if (tid < BN) sLab[tid] = g_lab[colBase + tid];
        __syncthreads();

        float c4[2][4][4];
#pragma unroll
        for (int mt = 0; mt < 2; mt++)
#pragma unroll
            for (int nt = 0; nt < 4; nt++)
#pragma unroll
                for (int e = 0; e < 4; e++) c4[mt][nt][e] = 0.f;

#pragma unroll
        for (int ks = 0; ks < DDIM/16; ks++) {
            uint32_t a[2][4], b[2][4];
            int kc = ks*2 + (lane >> 4);
#pragma unroll
            for (int mt = 0; mt < 2; mt++) {
                int row = wm*32 + mt*16 + (lane & 15);
                ldsm_x4(a[mt][0], a[mt][1], a[mt][2], a[mt][3],
                        sA_u + row*512 + ((kc ^ (row & 7)) << 4));
            }
#pragma unroll
            for (int bt = 0; bt < 2; bt++) {
                int nr = wn*32 + bt*16 + (lane & 15);
                ldsm_x4(b[bt][0], b[bt][1], b[bt][2], b[bt][3],
                        sB_u + nr*512 + ((kc ^ (nr & 7)) << 4));
            }
#pragma unroll
            for (int mt = 0; mt < 2; mt++)
#pragma unroll
                for (int nt = 0; nt < 4; nt++) {
                    int bt = nt >> 1, lo = nt & 1;
                    mma16816(c4[mt][nt][0], c4[mt][nt][1], c4[mt][nt][2], c4[mt][nt][3],
                             a[mt][0], a[mt][1], a[mt][2], a[mt][3],
                             b[bt][lo], b[bt][2+lo]);
                }
        }

        // epilogue: s = clip(dot/T); accumulate exp-sum / positive-sum / count
#pragma unroll
        for (int nt = 0; nt < 4; nt++) {
            int cl = wn*32 + nt*8 + q2;
            int labj0 = sLab[cl], labj1 = sLab[cl+1];
            int gj0 = colBase + cl;
#pragma unroll
            for (int mt = 0; mt < 2; mt++)
#pragma unroll
                for (int h = 0; h < 2; h++) {
                    int sl = mt*2 + h;
                    int gi = myrow[sl];
#pragma unroll
                    for (int jj = 0; jj < 2; jj++) {
                        float s = c4[mt][nt][h*2+jj] * invT;
                        s = fminf(fmaxf(s, -10.f), 10.f);
                        if (gi != gj0 + jj) {
                            accS[sl] += __expf(s - 10.f);
                            if ((jj ? labj1 : labj0) == mylab[sl]) {
                                accP[sl] += s; accC[sl]++;
                            }
                        }
                    }
                }
        }
    }

    // quad-reduce (lanes 4g..4g+3 share a row), deterministic partial stores
    const int buf = split*2 + wn;
#pragma unroll
    for (int sl = 0; sl < 4; sl++) {
        float s = accS[sl], p = accP[sl], cc = (float)accC[sl];
        s  += __shfl_xor_sync(0xffffffffu, s, 1);  s  += __shfl_xor_sync(0xffffffffu, s, 2);
        p  += __shfl_xor_sync(0xffffffffu, p, 1);  p  += __shfl_xor_sync(0xffffffffu, p, 2);
        cc += __shfl_xor_sync(0xffffffffu, cc, 1); cc += __shfl_xor_sync(0xffffffffu, cc, 2);
        if ((lane & 3) == 0) {
            g_sumP[buf][myrow[sl]] = s;
            g_posP[buf][myrow[sl]] = p;
            g_cntP[buf][myrow[sl]] = cc;
        }
    }
}

// ---------------- Phase 3: final reduction ------------------------------------
__global__ void reduce_kernel(float* __restrict__ out) {
    __shared__ float sL[256], sV[256];
    int tid = threadIdx.x;
    float lsum = 0.f, vsum = 0.f;
    for (int r = tid; r < NROWS; r += 256) {
        float s = 0.f, p = 0.f, cc = 0.f;
#pragma unroll
        for (int b = 0; b < NBUF; b++) {
            s += g_sumP[b][r]; p += g_posP[b][r]; cc += g_cntP[b][r];
        }
        if (cc > 0.f) {
            float lse = 10.f + logf(s);     // fixed max = 10 (sim clipped to <= 10)
            lsum += lse - p/cc;             // loss_i = -(pos_mean - lse)
            vsum += 1.f;
        }
    }
    sL[tid] = lsum; sV[tid] = vsum; __syncthreads();
    for (int o = 128; o > 0; o >>= 1) {
        if (tid < o) { sL[tid] += sL[tid+o]; sV[tid] += sV[tid+o]; }
        __syncthreads();
    }
    if (tid == 0) out[0] = (sV[0] > 0.f) ? sL[0]/sV[0] : 0.f;
}

// ---------------- launch ------------------------------------------------------
extern "C" void kernel_launch(void* const* d_in, const int* in_sizes, int n_in,
                              void* d_out, int out_size) {
    const float*     feat = (const float*)d_in[0];
    const long long* lab  = (const long long*)d_in[1];

    prep_kernel<<<NROWS/8, 256>>>(feat, lab);

    cudaFuncSetAttribute(gemm_fused_kernel,
                         cudaFuncAttributeMaxDynamicSharedMemorySize, SMEM_BYTES);
    dim3 grid(NROWS/BM, SPLIT);
    gemm_fused_kernel<<<grid, 256, SMEM_BYTES>>>();

    reduce_kernel<<<1, 256>>>((float*)d_out);
}

// round 6
// speedup vs baseline: 1.2332x; 1.2332x over previous
#include <cuda_runtime.h>
#include <cuda_bf16.h>
#include <cstdint>

#define NROWS 8192
#define DDIM  256
#define BM    128
#define BN    128
#define SPLIT 2
#define NTILES ((NROWS/SPLIT)/BN)     // 32 column tiles per CTA
#define THREADS 256
#define NBUF (SPLIT*4)                // (split, wn) partial buffers

#define SA_BYTES (BM*512)             // 65536: 128 rows x 512B swizzled
#define SB_BYTES (BN*512)             // 65536 per buffer
#define SMEM_BYTES (SA_BYTES + 2*SB_BYTES)   // 196608

__device__ __align__(16) __nv_bfloat16 g_fn[NROWS*DDIM];
__device__ unsigned char g_lab8[NROWS];
__device__ float g_sumP[NBUF][NROWS];
__device__ float g_posP[NBUF][NROWS];
__device__ float g_cntP[NBUF][NROWS];
__device__ float g_red[64][2];

// ---------------- PTX helpers -------------------------------------------------
__device__ __forceinline__ uint32_t smem_u32(const void* p) {
    uint32_t a;
    asm("{ .reg .u64 t; cvta.to.shared.u64 t, %1; cvt.u32.u64 %0, t; }" : "=r"(a) : "l"(p));
    return a;
}
__device__ __forceinline__ float ex2f(float x) {
    float r; asm("ex2.approx.f32 %0, %1;" : "=f"(r) : "f"(x)); return r;
}
__device__ __forceinline__ void cpasync16(uint32_t dst, const void* src) {
    asm volatile("cp.async.cg.shared.global [%0], [%1], 16;" :: "r"(dst), "l"(src));
}
#define CP_COMMIT() asm volatile("cp.async.commit_group;" ::: "memory")
#define CP_WAIT0()  asm volatile("cp.async.wait_group 0;" ::: "memory")

__device__ __forceinline__ void ldsm_x4(uint32_t& r0, uint32_t& r1, uint32_t& r2,
                                        uint32_t& r3, uint32_t addr) {
    asm volatile("ldmatrix.sync.aligned.m8n8.x4.shared.b16 {%0,%1,%2,%3}, [%4];\n"
                 : "=r"(r0), "=r"(r1), "=r"(r2), "=r"(r3) : "r"(addr));
}
__device__ __forceinline__ void mma16816(float& d0, float& d1, float& d2, float& d3,
                                         uint32_t a0, uint32_t a1, uint32_t a2,
                                         uint32_t a3, uint32_t b0, uint32_t b1) {
    asm volatile("mma.sync.aligned.m16n8k16.row.col.f32.bf16.bf16.f32 "
                 "{%0,%1,%2,%3}, {%4,%5,%6,%7}, {%8,%9}, {%0,%1,%2,%3};\n"
                 : "+f"(d0), "+f"(d1), "+f"(d2), "+f"(d3)
                 : "r"(a0), "r"(a1), "r"(a2), "r"(a3), "r"(b0), "r"(b1));
}

// ---------------- Phase 1: normalize rows -> bf16, labels -> bytes ------------
__global__ void prep_kernel(const float* __restrict__ feat,
                            const long long* __restrict__ lab) {
    int row  = (blockIdx.x * blockDim.x + threadIdx.x) >> 5;
    int lane = threadIdx.x & 31;
    if (row >= NROWS) return;
    float v[8]; float ss = 0.f;
#pragma unroll
    for (int i = 0; i < 8; i++) {
        float x = feat[row*DDIM + i*32 + lane];
        v[i] = x; ss += x*x;
    }
#pragma unroll
    for (int o = 16; o > 0; o >>= 1) ss += __shfl_xor_sync(0xffffffffu, ss, o);
    float scale = 1.f / fmaxf(sqrtf(ss), 1e-6f);
#pragma unroll
    for (int i = 0; i < 8; i++)
        g_fn[row*DDIM + i*32 + lane] = __float2bfloat16(v[i]*scale);
    if (lane == 0) g_lab8[row] = (unsigned char)lab[row];
}

// ---------------- Phase 2: pipelined mma.sync GEMM + softmax stats ------------
// grid (NROWS/BM=64, SPLIT=2) = 128 CTAs (one wave). 256 thr = 8 warps: 2(m) x 4(n),
// warp tile 64x32. B double-buffered via cp.async; A persistent in smem.
__global__ void __launch_bounds__(256, 1) gemm_fused_kernel() {
    extern __shared__ char smem[];
    const uint32_t sA_u = smem_u32(smem);
    const uint32_t sB_u = sA_u + SA_BYTES;

    const int tid  = threadIdx.x;
    const int warp = tid >> 5, lane = tid & 31;
    const int wm = warp >> 2, wn = warp & 3;      // 2 x 4
    const int g  = lane >> 2;                     // row within 8-group
    const int q2 = (lane & 3) * 2;                // col pair within n8

    const int rowBase  = blockIdx.x * BM;
    const int split    = blockIdx.y;
    const int colStart = split * (NROWS / SPLIT);

    // ---- prefetch B tile 0 (buffer 0) ----
    {
        const int colBase = colStart;
#pragma unroll
        for (int it = 0; it < (BN*32)/THREADS; it++) {
            int idx = tid + it*THREADS;
            int r = idx >> 5, c = idx & 31;
            cpasync16(sB_u + r*512 + ((c ^ (r & 7)) << 4),
                      (const char*)(g_fn + (size_t)(colBase + r)*DDIM) + c*16);
        }
        CP_COMMIT();
    }

    // ---- load A tile (persistent, swizzled) ----
    for (int idx = tid; idx < BM*32; idx += THREADS) {
        int r = idx >> 5, c = idx & 31;
        uint4 val = ((const uint4*)(g_fn + (size_t)(rowBase + r)*DDIM))[c];
        *((uint4*)(smem + r*512 + ((c ^ (r & 7)) << 4))) = val;
    }

    // rows this thread owns (8): wm*64 + mt*16 + h*8 + g
    int myrow[8], mylab[8];
#pragma unroll
    for (int mt = 0; mt < 4; mt++)
#pragma unroll
        for (int h = 0; h < 2; h++) {
            int rl = wm*64 + mt*16 + h*8 + g;
            myrow[mt*2+h] = rowBase + rl;
            mylab[mt*2+h] = g_lab8[rowBase + rl];
        }

    float accS[8], accP[8]; int accC[8];
#pragma unroll
    for (int i = 0; i < 8; i++) { accS[i] = 0.f; accP[i] = 0.f; accC[i] = 0; }

    const float invT = 1.0f/0.07f;
    const float K1 = invT * 1.44269504f;           // invT * log2(e)
    const float K2 = -10.0f * 1.44269504f;

    for (int j = 0; j < NTILES; j++) {
        const int buf = j & 1;
        const int colBase = colStart + j*BN;
        const uint32_t sBc = sB_u + buf*SB_BYTES;

        CP_WAIT0();            // tile j resident
        __syncthreads();       // all warps done with compute on buffer buf^1

        if (j + 1 < NTILES) {  // prefetch j+1 into the other buffer (overlaps compute)
            const uint32_t sBn = sB_u + (buf^1)*SB_BYTES;
            const int nb = colBase + BN;
#pragma unroll
            for (int it = 0; it < (BN*32)/THREADS; it++) {
                int idx = tid + it*THREADS;
                int r = idx >> 5, c = idx & 31;
                cpasync16(sBn + r*512 + ((c ^ (r & 7)) << 4),
                          (const char*)(g_fn + (size_t)(nb + r)*DDIM) + c*16);
            }
            CP_COMMIT();
        }

        // ---- GEMM: warp tile 64x32, k = 256 ----
        float c4[4][4][4];
#pragma unroll
        for (int mt = 0; mt < 4; mt++)
#pragma unroll
            for (int nt = 0; nt < 4; nt++)
#pragma unroll
                for (int e = 0; e < 4; e++) c4[mt][nt][e] = 0.f;

#pragma unroll
        for (int ks = 0; ks < DDIM/16; ks++) {
            uint32_t a[4][4], b[2][4];
            int kc = ks*2 + (lane >> 4);
#pragma unroll
            for (int mt = 0; mt < 4; mt++) {
                int row = wm*64 + mt*16 + (lane & 15);
                ldsm_x4(a[mt][0], a[mt][1], a[mt][2], a[mt][3],
                        sA_u + row*512 + ((kc ^ (row & 7)) << 4));
            }
#pragma unroll
            for (int bt = 0; bt < 2; bt++) {
                int nr = wn*32 + bt*16 + (lane & 15);
                ldsm_x4(b[bt][0], b[bt][1], b[bt][2], b[bt][3],
                        sBc + nr*512 + ((kc ^ (nr & 7)) << 4));
            }
#pragma unroll
            for (int mt = 0; mt < 4; mt++)
#pragma unroll
                for (int nt = 0; nt < 4; nt++) {
                    int bt = nt >> 1, lo = nt & 1;
                    mma16816(c4[mt][nt][0], c4[mt][nt][1], c4[mt][nt][2], c4[mt][nt][3],
                             a[mt][0], a[mt][1], a[mt][2], a[mt][3],
                             b[bt][lo], b[bt][2+lo]);
                }
        }

        // ---- epilogue: exp-sum / positive-sum / count ----
        const bool diagTile = (colBase == rowBase);
#pragma unroll
        for (int nt = 0; nt < 4; nt++) {
            const int cl = wn*32 + nt*8 + q2;
            const int gj0 = colBase + cl;
            const int labj0 = __ldg(g_lab8 + gj0);
            const int labj1 = __ldg(g_lab8 + gj0 + 1);
            if (!diagTile) {
#pragma unroll
                for (int mt = 0; mt < 4; mt++)
#pragma unroll
                    for (int h = 0; h < 2; h++) {
                        const int sl = mt*2 + h;
#pragma unroll
                        for (int jj = 0; jj < 2; jj++) {
                            float dv = c4[mt][nt][h*2+jj];
                            float arg = fminf(fmaf(dv, K1, K2), 0.f);  // clip s<=10
                            accS[sl] += ex2f(arg);
                            if ((jj ? labj1 : labj0) == mylab[sl]) {
                                accP[sl] = fmaf(dv, invT, accP[sl]);
                                accC[sl]++;
                            }
                        }
                    }
            } else {
#pragma unroll
                for (int mt = 0; mt < 4; mt++)
#pragma unroll
                    for (int h = 0; h < 2; h++) {
                        const int sl = mt*2 + h;
                        const int gi = myrow[sl];
#pragma unroll
                        for (int jj = 0; jj < 2; jj++) {
                            bool keep = (gi != gj0 + jj);
                            float dv = c4[mt][nt][h*2+jj];
                            float arg = fminf(fmaf(dv, K1, K2), 0.f);
                            if (keep) accS[sl] += ex2f(arg);
                            if (keep && ((jj ? labj1 : labj0) == mylab[sl])) {
                                accP[sl] = fmaf(dv, invT, accP[sl]);
                                accC[sl]++;
                            }
                        }
                    }
            }
        }
    }

    // quad-reduce (lanes of a quad share rows, differ in cols), deterministic stores
    const int bufIdx = split*4 + wn;
#pragma unroll
    for (int sl = 0; sl < 8; sl++) {
        float s = accS[sl], p = accP[sl], cc = (float)accC[sl];
        s  += __shfl_xor_sync(0xffffffffu, s, 1);  s  += __shfl_xor_sync(0xffffffffu, s, 2);
        p  += __shfl_xor_sync(0xffffffffu, p, 1);  p  += __shfl_xor_sync(0xffffffffu, p, 2);
        cc += __shfl_xor_sync(0xffffffffu, cc, 1); cc += __shfl_xor_sync(0xffffffffu, cc, 2);
        if ((lane & 3) == 0) {
            g_sumP[bufIdx][myrow[sl]] = s;
            g_posP[bufIdx][myrow[sl]] = p;
            g_cntP[bufIdx][myrow[sl]] = cc;
        }
    }
}

// ---------------- Phase 3: reduction (two-stage, deterministic) ---------------
__global__ void reduce1_kernel() {
    __shared__ float sL[128], sV[128];
    int tid = threadIdx.x;
    int row = blockIdx.x * 128 + tid;
    float s = 0.f, p = 0.f, cc = 0.f;
#pragma unroll
    for (int b = 0; b < NBUF; b++) {
        s += g_sumP[b][row]; p += g_posP[b][row]; cc += g_cntP[b][row];
    }
    float l = 0.f, v = 0.f;
    if (cc > 0.f) { l = 10.f + logf(s) - p/cc; v = 1.f; }
    sL[tid] = l; sV[tid] = v; __syncthreads();
    for (int o = 64; o > 0; o >>= 1) {
        if (tid < o) { sL[tid] += sL[tid+o]; sV[tid] += sV[tid+o]; }
        __syncthreads();
    }
    if (tid == 0) { g_red[blockIdx.x][0] = sL[0]; g_red[blockIdx.x][1] = sV[0]; }
}

__global__ void reduce2_kernel(float* __restrict__ out) {
    __shared__ float sL[64], sV[64];
    int tid = threadIdx.x;
    sL[tid] = g_red[tid][0]; sV[tid] = g_red[tid][1];
    __syncthreads();
    for (int o = 32; o > 0; o >>= 1) {
        if (tid < o) { sL[tid] += sL[tid+o]; sV[tid] += sV[tid+o]; }
        __syncthreads();
    }
    if (tid == 0) out[0] = (sV[0] > 0.f) ? sL[0]/sV[0] : 0.f;
}

// ---------------- launch ------------------------------------------------------
extern "C" void kernel_launch(void* const* d_in, const int* in_sizes, int n_in,
                              void* d_out, int out_size) {
    const float*     feat = (const float*)d_in[0];
    const long long* lab  = (const long long*)d_in[1];

    prep_kernel<<<NROWS/8, 256>>>(feat, lab);

    cudaFuncSetAttribute(gemm_fused_kernel,
                         cudaFuncAttributeMaxDynamicSharedMemorySize, SMEM_BYTES);
    dim3 grid(NROWS/BM, SPLIT);
    gemm_fused_kernel<<<grid, 256, SMEM_BYTES>>>();

    reduce1_kernel<<<64, 128>>>();
    reduce2_kernel<<<1, 64>>>((float*)d_out);
}

// round 7
// speedup vs baseline: 1.3037x; 1.0571x over previous
#include <cuda_runtime.h>
#include <cuda_bf16.h>
#include <cstdint>

#define NROWS 8192
#define DDIM  256
#define BM    128
#define BN    128
#define SPLIT 2
#define NTILES ((NROWS/SPLIT)/BN)     // 32 column tiles per CTA
#define THREADS 512
#define NBUF (SPLIT*4)                // (split, wn) partial buffers

#define SA_BYTES (BM*512)             // 65536: 128 rows x 512B swizzled
#define SB_BYTES (BN*512)             // 65536 per buffer
#define SMEM_BYTES (SA_BYTES + 2*SB_BYTES)   // 196608

__device__ __align__(16) __nv_bfloat16 g_fn[NROWS*DDIM];
__device__ unsigned char g_lab8[NROWS];
__device__ float g_sumP[NBUF][NROWS];
__device__ float g_posP[NBUF][NROWS];
__device__ float g_cntP[NBUF][NROWS];
__device__ float g_red[64][2];
__device__ unsigned int g_ctr;

// ---------------- PTX helpers -------------------------------------------------
__device__ __forceinline__ uint32_t smem_u32(const void* p) {
    uint32_t a;
    asm("{ .reg .u64 t; cvta.to.shared.u64 t, %1; cvt.u32.u64 %0, t; }" : "=r"(a) : "l"(p));
    return a;
}
__device__ __forceinline__ float ex2f(float x) {
    float r; asm("ex2.approx.f32 %0, %1;" : "=f"(r) : "f"(x)); return r;
}
__device__ __forceinline__ void cpasync16(uint32_t dst, const void* src) {
    asm volatile("cp.async.cg.shared.global [%0], [%1], 16;" :: "r"(dst), "l"(src));
}
#define CP_COMMIT() asm volatile("cp.async.commit_group;" ::: "memory")
#define CP_WAIT0()  asm volatile("cp.async.wait_group 0;" ::: "memory")

__device__ __forceinline__ void ldsm_x4(uint32_t& r0, uint32_t& r1, uint32_t& r2,
                                        uint32_t& r3, uint32_t addr) {
    asm volatile("ldmatrix.sync.aligned.m8n8.x4.shared.b16 {%0,%1,%2,%3}, [%4];\n"
                 : "=r"(r0), "=r"(r1), "=r"(r2), "=r"(r3) : "r"(addr));
}
__device__ __forceinline__ void mma16816(float& d0, float& d1, float& d2, float& d3,
                                         uint32_t a0, uint32_t a1, uint32_t a2,
                                         uint32_t a3, uint32_t b0, uint32_t b1) {
    asm volatile("mma.sync.aligned.m16n8k16.row.col.f32.bf16.bf16.f32 "
                 "{%0,%1,%2,%3}, {%4,%5,%6,%7}, {%8,%9}, {%0,%1,%2,%3};\n"
                 : "+f"(d0), "+f"(d1), "+f"(d2), "+f"(d3)
                 : "r"(a0), "r"(a1), "r"(a2), "r"(a3), "r"(b0), "r"(b1));
}

// ---------------- Phase 1: normalize rows -> bf16, labels -> bytes ------------
__global__ void prep_kernel(const float* __restrict__ feat,
                            const long long* __restrict__ lab) {
    int row  = (blockIdx.x * blockDim.x + threadIdx.x) >> 5;
    int lane = threadIdx.x & 31;
    if (row >= NROWS) return;
    const float4* fp = (const float4*)(feat + (size_t)row*DDIM);
    float4 x0 = fp[lane], x1 = fp[lane + 32];
    float ss = x0.x*x0.x + x0.y*x0.y + x0.z*x0.z + x0.w*x0.w
             + x1.x*x1.x + x1.y*x1.y + x1.z*x1.z + x1.w*x1.w;
#pragma unroll
    for (int o = 16; o > 0; o >>= 1) ss += __shfl_xor_sync(0xffffffffu, ss, o);
    float sc = 1.f / fmaxf(sqrtf(ss), 1e-6f);
    __nv_bfloat162* bp = (__nv_bfloat162*)(g_fn + (size_t)row*DDIM);
    bp[lane*2+0]  = __floats2bfloat162_rn(x0.x*sc, x0.y*sc);
    bp[lane*2+1]  = __floats2bfloat162_rn(x0.z*sc, x0.w*sc);
    bp[64+lane*2+0] = __floats2bfloat162_rn(x1.x*sc, x1.y*sc);
    bp[64+lane*2+1] = __floats2bfloat162_rn(x1.z*sc, x1.w*sc);
    if (lane == 0) g_lab8[row] = (unsigned char)lab[row];
}

// ---------------- Phase 2: pipelined mma.sync GEMM + softmax stats ------------
// grid (64, 2) = 128 CTAs (one wave). 512 thr = 16 warps: 4(m) x 4(n),
// warp tile 32x32 (4 warps/SMSP for latency coverage). B double-buffered cp.async.
__global__ void __launch_bounds__(512, 1) gemm_fused_kernel() {
    extern __shared__ char smem[];
    const uint32_t sA_u = smem_u32(smem);
    const uint32_t sB_u = sA_u + SA_BYTES;

    const int tid  = threadIdx.x;
    const int warp = tid >> 5, lane = tid & 31;
    const int wm = warp >> 2, wn = warp & 3;      // 4 x 4
    const int g  = lane >> 2;                     // row within 8-group
    const int q2 = (lane & 3) * 2;                // col pair within n8

    const int rowBase  = blockIdx.x * BM;
    const int split    = blockIdx.y;
    const int colStart = split * (NROWS / SPLIT);

    // ---- prefetch B tile 0 (buffer 0) ----
    {
#pragma unroll
        for (int it = 0; it < (BN*32)/THREADS; it++) {
            int idx = tid + it*THREADS;
            int r = idx >> 5, c = idx & 31;
            cpasync16(sB_u + r*512 + ((c ^ (r & 7)) << 4),
                      (const char*)(g_fn + (size_t)(colStart + r)*DDIM) + c*16);
        }
        CP_COMMIT();
    }

    // ---- load A tile (persistent, swizzled) ----
    for (int idx = tid; idx < BM*32; idx += THREADS) {
        int r = idx >> 5, c = idx & 31;
        uint4 val = ((const uint4*)(g_fn + (size_t)(rowBase + r)*DDIM))[c];
        *((uint4*)(smem + r*512 + ((c ^ (r & 7)) << 4))) = val;
    }

    // rows this thread owns (4): wm*32 + mt*16 + h*8 + g
    int myrow[4], mylab[4];
#pragma unroll
    for (int mt = 0; mt < 2; mt++)
#pragma unroll
        for (int h = 0; h < 2; h++) {
            int rl = wm*32 + mt*16 + h*8 + g;
            myrow[mt*2+h] = rowBase + rl;
            mylab[mt*2+h] = g_lab8[rowBase + rl];
        }

    float accS[4] = {0,0,0,0}, accP[4] = {0,0,0,0};
    int accC[4] = {0,0,0,0};

    const float invT = 1.0f/0.07f;
    const float K1 = invT * 1.44269504f;           // invT * log2(e)
    const float K2 = -10.0f * 1.44269504f;

    for (int j = 0; j < NTILES; j++) {
        const int buf = j & 1;
        const int colBase = colStart + j*BN;
        const uint32_t sBc = sB_u + buf*SB_BYTES;

        CP_WAIT0();            // tile j resident
        __syncthreads();       // all warps done with buffer buf^1

        if (j + 1 < NTILES) {  // prefetch j+1 (overlaps this tile's compute)
            const uint32_t sBn = sB_u + (buf^1)*SB_BYTES;
            const int nb = colBase + BN;
#pragma unroll
            for (int it = 0; it < (BN*32)/THREADS; it++) {
                int idx = tid + it*THREADS;
                int r = idx >> 5, c = idx & 31;
                cpasync16(sBn + r*512 + ((c ^ (r & 7)) << 4),
                          (const char*)(g_fn + (size_t)(nb + r)*DDIM) + c*16);
            }
            CP_COMMIT();
        }

        // ---- GEMM: warp tile 32x32, k = 256 ----
        float c4[2][4][4];
#pragma unroll
        for (int mt = 0; mt < 2; mt++)
#pragma unroll
            for (int nt = 0; nt < 4; nt++)
#pragma unroll
                for (int e = 0; e < 4; e++) c4[mt][nt][e] = 0.f;

#pragma unroll
        for (int ks = 0; ks < DDIM/16; ks++) {
            uint32_t a[2][4], b[2][4];
            int kc = ks*2 + (lane >> 4);
#pragma unroll
            for (int mt = 0; mt < 2; mt++) {
                int row = wm*32 + mt*16 + (lane & 15);
                ldsm_x4(a[mt][0], a[mt][1], a[mt][2], a[mt][3],
                        sA_u + row*512 + ((kc ^ (row & 7)) << 4));
            }
#pragma unroll
            for (int bt = 0; bt < 2; bt++) {
                int nr = wn*32 + bt*16 + (lane & 15);
                ldsm_x4(b[bt][0], b[bt][1], b[bt][2], b[bt][3],
                        sBc + nr*512 + ((kc ^ (nr & 7)) << 4));
            }
#pragma unroll
            for (int mt = 0; mt < 2; mt++)
#pragma unroll
                for (int nt = 0; nt < 4; nt++) {
                    int bt = nt >> 1, lo = nt & 1;
                    mma16816(c4[mt][nt][0], c4[mt][nt][1], c4[mt][nt][2], c4[mt][nt][3],
                             a[mt][0], a[mt][1], a[mt][2], a[mt][3],
                             b[bt][lo], b[bt][2+lo]);
                }
        }

        // ---- epilogue ----
        const bool diagTile = (colBase == rowBase);
#pragma unroll
        for (int nt = 0; nt < 4; nt++) {
            const int cl = wn*32 + nt*8 + q2;
            const int gj0 = colBase + cl;
            const int labj0 = __ldg(g_lab8 + gj0);
            const int labj1 = __ldg(g_lab8 + gj0 + 1);
            if (!diagTile) {
#pragma unroll
                for (int mt = 0; mt < 2; mt++)
#pragma unroll
                    for (int h = 0; h < 2; h++) {
                        const int sl = mt*2 + h;
#pragma unroll
                        for (int jj = 0; jj < 2; jj++) {
                            float dv = c4[mt][nt][h*2+jj];
                            float arg = fminf(fmaf(dv, K1, K2), 0.f);  // s <= 10 clip
                            accS[sl] += ex2f(arg);
                            if ((jj ? labj1 : labj0) == mylab[sl]) {
                                accP[sl] = fmaf(dv, invT, accP[sl]);
                                accC[sl]++;
                            }
                        }
                    }
            } else {
#pragma unroll
                for (int mt = 0; mt < 2; mt++)
#pragma unroll
                    for (int h = 0; h < 2; h++) {
                        const int sl = mt*2 + h;
                        const int gi = myrow[sl];
#pragma unroll
                        for (int jj = 0; jj < 2; jj++) {
                            bool keep = (gi != gj0 + jj);
                            float dv = c4[mt][nt][h*2+jj];
                            float arg = fminf(fmaf(dv, K1, K2), 0.f);
                            if (keep) accS[sl] += ex2f(arg);
                            if (keep && ((jj ? labj1 : labj0) == mylab[sl])) {
                                accP[sl] = fmaf(dv, invT, accP[sl]);
                                accC[sl]++;
                            }
                        }
                    }
            }
        }
    }

    // quad-reduce (lanes of a quad share rows), deterministic stores
    const int bufIdx = split*4 + wn;
#pragma unroll
    for (int sl = 0; sl < 4; sl++) {
        float s = accS[sl], p = accP[sl], cc = (float)accC[sl];
        s  += __shfl_xor_sync(0xffffffffu, s, 1);  s  += __shfl_xor_sync(0xffffffffu, s, 2);
        p  += __shfl_xor_sync(0xffffffffu, p, 1);  p  += __shfl_xor_sync(0xffffffffu, p, 2);
        cc += __shfl_xor_sync(0xffffffffu, cc, 1); cc += __shfl_xor_sync(0xffffffffu, cc, 2);
        if ((lane & 3) == 0) {
            g_sumP[bufIdx][myrow[sl]] = s;
            g_posP[bufIdx][myrow[sl]] = p;
            g_cntP[bufIdx][myrow[sl]] = cc;
        }
    }
}

// ---------------- Phase 3: fused reduction (last-block-done) ------------------
__global__ void reduce_kernel(float* __restrict__ out) {
    __shared__ float sL[128], sV[128];
    __shared__ unsigned int isLast;
    int tid = threadIdx.x;
    int row = blockIdx.x * 128 + tid;
    float s = 0.f, p = 0.f, cc = 0.f;
#pragma unroll
    for (int b = 0; b < NBUF; b++) {
        s += g_sumP[b][row]; p += g_posP[b][row]; cc += g_cntP[b][row];
    }
    float l = 0.f, v = 0.f;
    if (cc > 0.f) { l = 10.f + logf(s) - p/cc; v = 1.f; }
    sL[tid] = l; sV[tid] = v; __syncthreads();
    for (int o = 64; o > 0; o >>= 1) {
        if (tid < o) { sL[tid] += sL[tid+o]; sV[tid] += sV[tid+o]; }
        __syncthreads();
    }
    if (tid == 0) {
        g_red[blockIdx.x][0] = sL[0]; g_red[blockIdx.x][1] = sV[0];
        __threadfence();
        isLast = (atomicAdd(&g_ctr, 1u) == 63u);
    }
    __syncthreads();
    if (isLast) {
        if (tid < 64) { sL[tid] = g_red[tid][0]; sV[tid] = g_red[tid][1]; }
        __syncthreads();
        for (int o = 32; o > 0; o >>= 1) {
            if (tid < o && tid + o < 64) { sL[tid] += sL[tid+o]; sV[tid] += sV[tid+o]; }
            __syncthreads();
        }
        if (tid == 0) {
            out[0] = (sV[0] > 0.f) ? sL[0]/sV[0] : 0.f;
            g_ctr = 0;          // reset for next graph replay
        }
    }
}

// ---------------- launch ------------------------------------------------------
extern "C" void kernel_launch(void* const* d_in, const int* in_sizes, int n_in,
                              void* d_out, int out_size) {
    const float*     feat = (const float*)d_in[0];
    const long long* lab  = (const long long*)d_in[1];

    prep_kernel<<<NROWS/8, 256>>>(feat, lab);

    cudaFuncSetAttribute(gemm_fused_kernel,
                         cudaFuncAttributeMaxDynamicSharedMemorySize, SMEM_BYTES);
    dim3 grid(NROWS/BM, SPLIT);
    gemm_fused_kernel<<<grid, THREADS, SMEM_BYTES>>>();

    reduce_kernel<<<64, 128>>>((float*)d_out);
}